// round 16
// baseline (speedup 1.0000x reference)
#include <cuda_runtime.h>
#include <cstdint>

#define NN 100000
#define EE 3200000
#define D_IN 512
#define D_HID 16
#define N_CLS 7

typedef unsigned long long ull;

// Scratch (device globals: allocation-free per harness rules)
__device__ __align__(16) float g_h1[NN * D_HID];     // x @ W1
__device__ __align__(16) float g_agg1[NN * D_HID];   // scatter-add of h1
__device__ __align__(16) float g_h2[NN * 8];         // relu(agg1+b1) @ W2, padded 7->8
__device__ __align__(16) float g_agg2[NN * 8];       // scatter-add of h2, padded
__device__ int g_is64;                               // edge-index dtype flag

__device__ __forceinline__ void red_add_v4(float* addr, float4 v) {
    asm volatile("{ .reg .u64 ga;\n\t"
                 "cvta.to.global.u64 ga, %0;\n\t"
                 "red.global.add.v4.f32 [ga], {%1,%2,%3,%4}; }"
                 :: "l"(addr), "f"(v.x), "f"(v.y), "f"(v.z), "f"(v.w)
                 : "memory");
}

__device__ __forceinline__ uint32_t smem_u32(const void* p) {
    uint32_t a;
    asm("{ .reg .u64 t; cvta.to.shared.u64 t, %1; cvt.u32.u64 %0, t; }"
        : "=r"(a) : "l"(p));
    return a;
}
__device__ __forceinline__ void cpa16(uint32_t dst, const void* src) {
    asm volatile("cp.async.cg.shared.global [%0], [%1], 16;" :: "r"(dst), "l"(src));
}
__device__ __forceinline__ void cpa_commit() { asm volatile("cp.async.commit_group;"); }
template <int N>
__device__ __forceinline__ void cpa_wait() {
    asm volatile("cp.async.wait_group %0;" :: "n"(N));
}

__device__ __forceinline__ uint32_t cvt_tf32(float f) {
    uint32_t r;
    asm("cvt.rna.tf32.f32 %0, %1;" : "=r"(r) : "f"(f));
    return r;
}
__device__ __forceinline__ void mma_tf32(float c[4],
                                         uint32_t a0, uint32_t a1, uint32_t a2, uint32_t a3,
                                         uint32_t b0, uint32_t b1) {
    asm volatile(
        "mma.sync.aligned.m16n8k8.row.col.f32.tf32.tf32.f32 "
        "{%0,%1,%2,%3}, {%4,%5,%6,%7}, {%8,%9}, {%0,%1,%2,%3};"
        : "+f"(c[0]), "+f"(c[1]), "+f"(c[2]), "+f"(c[3])
        : "r"(a0), "r"(a1), "r"(a2), "r"(a3), "r"(b0), "r"(b1));
}

// ---------------------------------------------------------------------------
// GEMM1 via tensor cores (tf32 mma.sync). Warp = 32 nodes x 16 outputs.
// x tile double-buffered in smem via cp.async; W1 staged raw, scaled+rounded
// at fragment build: cvt.rna(tf32, w*(1+2^-11)) compensates the truncation
// bias of feeding RAW fp32 x bits to the mma (no cvt on the x side).
// ALSO: zeroes this block's agg1 rows (replaces k_init) and block 0 does
// the edge-dtype detect (g_is64 consumed only by later scatter kernels).
// ---------------------------------------------------------------------------
#define G1_T   128
#define G1_KC  32
#define G1_NCH (D_IN / G1_KC)
#define G1_XP  36                 // x row pitch (bank 4g+t conflict-free)
#define G1_WP  20                 // W row pitch: 80B rows, 16B-aligned quarters
#define G1_BLOCKS ((NN + G1_T - 1) / G1_T)   // 782

__global__ __launch_bounds__(G1_T) void k_gemm1(const float* __restrict__ x,
                                                const float* __restrict__ W1,
                                                const int* __restrict__ ei32) {
    __shared__ float xs[2][G1_T][G1_XP];    // 36,864 B
    __shared__ float wsc[2][G1_KC][G1_WP];  //  5,120 B

    int tid = threadIdx.x;
    int w = tid >> 5, lane = tid & 31;
    int g = lane >> 2, t = lane & 3;
    int nbase = blockIdx.x * G1_T;

    // Edge dtype detect (block 0 only; consumed by scatter kernels later).
    if (blockIdx.x == 0 && tid == 0) {
        int s = 0;
        #pragma unroll
        for (int q = 1; q < 64; q += 2) s |= ei32[q];
        g_is64 = (s == 0) ? 1 : 0;
    }

    auto stage = [&](int kc, int b) {
        #pragma unroll
        for (int r = 0; r < 8; r++) {
            int idx = r * G1_T + tid;
            int mm  = idx >> 3;
            int kk4 = (idx & 7) * 4;
            int gm  = nbase + mm;
            if (gm < NN)
                cpa16(smem_u32(&xs[b][mm][kk4]),
                      x + (size_t)gm * D_IN + kc * G1_KC + kk4);
        }
        int k = tid >> 2, q = tid & 3;
        cpa16(smem_u32(&wsc[b][k][q * 4]),          // 80k + 16q bytes: aligned
              W1 + (size_t)(kc * G1_KC + k) * 16 + q * 4);
    };

    float c[2][2][4];
    #pragma unroll
    for (int mt = 0; mt < 2; mt++)
        #pragma unroll
        for (int nt = 0; nt < 2; nt++)
            #pragma unroll
            for (int i = 0; i < 4; i++) c[mt][nt][i] = 0.f;

    stage(0, 0);
    cpa_commit();

    // Zero this block's agg1 rows (replaces k_init's agg1 memset).
    // 128 nodes x 16 floats = 512 float4; 4 per thread. Overlaps the first
    // cp.async group's flight time.
    {
        float4 z = make_float4(0.f, 0.f, 0.f, 0.f);
        #pragma unroll
        for (int r = 0; r < 4; r++) {
            int idx = r * G1_T + tid;              // 0..511
            int gm  = nbase + (idx >> 2);
            if (gm < NN)
                reinterpret_cast<float4*>(g_agg1)[(size_t)nbase * 4 + idx] = z;
        }
    }

    for (int kc = 0; kc < G1_NCH; kc++) {
        int b = kc & 1;
        if (kc < G1_NCH - 1) {
            stage(kc + 1, (kc + 1) & 1);
            cpa_commit();
            cpa_wait<1>();
        } else {
            cpa_wait<0>();
        }
        __syncthreads();

        #pragma unroll
        for (int ks = 0; ks < 4; ks++) {
            int k0 = ks * 8;
            // B fragments: raw W -> scale (bias compensation) -> tf32 round
            uint32_t bf[2][2];
            #pragma unroll
            for (int nt = 0; nt < 2; nt++) {
                bf[nt][0] = cvt_tf32(wsc[b][k0 + t][nt * 8 + g] * 1.00048828125f);
                bf[nt][1] = cvt_tf32(wsc[b][k0 + t + 4][nt * 8 + g] * 1.00048828125f);
            }
            #pragma unroll
            for (int mt = 0; mt < 2; mt++) {
                int rr = w * 32 + mt * 16 + g;
                // A fragments: RAW fp32 bits (tf32 truncation, bias-compensated)
                uint32_t a0 = __float_as_uint(xs[b][rr][k0 + t]);
                uint32_t a1 = __float_as_uint(xs[b][rr + 8][k0 + t]);
                uint32_t a2 = __float_as_uint(xs[b][rr][k0 + t + 4]);
                uint32_t a3 = __float_as_uint(xs[b][rr + 8][k0 + t + 4]);
                #pragma unroll
                for (int nt = 0; nt < 2; nt++)
                    mma_tf32(c[mt][nt], a0, a1, a2, a3, bf[nt][0], bf[nt][1]);
            }
        }
        __syncthreads();
    }

    // Epilogue: lane owns (rows g, g+8; cols 2t, 2t+1) per tile.
    #pragma unroll
    for (int mt = 0; mt < 2; mt++) {
        int node = nbase + w * 32 + mt * 16 + g;
        #pragma unroll
        for (int nt = 0; nt < 2; nt++) {
            if (node < NN) {
                float2 v = make_float2(c[mt][nt][0], c[mt][nt][1]);
                *reinterpret_cast<float2*>(g_h1 + (size_t)node * 16 + nt * 8 + 2 * t) = v;
            }
            if (node + 8 < NN) {
                float2 v = make_float2(c[mt][nt][2], c[mt][nt][3]);
                *reinterpret_cast<float2*>(g_h1 + (size_t)(node + 8) * 16 + nt * 8 + 2 * t) = v;
            }
        }
    }
}

// ---------------------------------------------------------------------------
// Scatter1: agg1[dst] += h1[src].  4 lanes per edge, 8 edges per warp.
// ---------------------------------------------------------------------------
__global__ __launch_bounds__(256) void k_scatter1(const void* __restrict__ ei) {
    int warpGlobal = (blockIdx.x * 256 + threadIdx.x) >> 5;
    int lane = threadIdx.x & 31;
    int e_base = warpGlobal * 8;                  // EE = 50000*8*8 exactly
    int s = 0, d = 0;
    if (lane < 8) {
        int e = e_base + lane;
        if (g_is64) {
            const long long* p = (const long long*)ei;
            s = (int)p[e];
            d = (int)p[EE + e];
        } else {
            const int* p = (const int*)ei;
            s = p[e];
            d = p[EE + e];
        }
    }
    int eloc = lane >> 2;
    int src = __shfl_sync(0xffffffffu, s, eloc);
    int dst = __shfl_sync(0xffffffffu, d, eloc);
    if ((unsigned)src >= NN || (unsigned)dst >= NN) return;
    int chunk = lane & 3;
    float4 v = reinterpret_cast<const float4*>(g_h1)[src * 4 + chunk];
    red_add_v4(g_agg1 + (size_t)dst * 16 + chunk * 4, v);
}

// ---------------------------------------------------------------------------
// GEMM2: g_h2 = relu(agg1 + b1) @ W2 (rows padded to 8). Also zeroes agg2[n]
// (replaces k_init's agg2 memset; gemm2 completes before scatter2 launches).
// ---------------------------------------------------------------------------
__global__ __launch_bounds__(256) void k_gemm2(const float* __restrict__ b1,
                                               const float* __restrict__ W2) {
    __shared__ float w2s[16 * 7];
    __shared__ float b1s[16];
    if (threadIdx.x < 112) w2s[threadIdx.x] = W2[threadIdx.x];
    if (threadIdx.x < 16)  b1s[threadIdx.x] = b1[threadIdx.x];
    __syncthreads();

    int n = blockIdx.x * blockDim.x + threadIdx.x;
    if (n >= NN) return;

    // Zero agg2 row for this node (consumed by scatter2's atomics).
    float4 z = make_float4(0.f, 0.f, 0.f, 0.f);
    reinterpret_cast<float4*>(g_agg2)[(size_t)n * 2]     = z;
    reinterpret_cast<float4*>(g_agg2)[(size_t)n * 2 + 1] = z;

    const float4* ap = reinterpret_cast<const float4*>(g_agg1 + (size_t)n * 16);
    float h[16];
    float4 t0 = ap[0], t1 = ap[1], t2 = ap[2], t3 = ap[3];
    h[0] = t0.x; h[1] = t0.y; h[2]  = t0.z; h[3]  = t0.w;
    h[4] = t1.x; h[5] = t1.y; h[6]  = t1.z; h[7]  = t1.w;
    h[8] = t2.x; h[9] = t2.y; h[10] = t2.z; h[11] = t2.w;
    h[12] = t3.x; h[13] = t3.y; h[14] = t3.z; h[15] = t3.w;
    #pragma unroll
    for (int j = 0; j < 16; j++) h[j] = fmaxf(h[j] + b1s[j], 0.f);

    float o[8];
    #pragma unroll
    for (int c = 0; c < 7; c++) {
        float s = 0.f;
        #pragma unroll
        for (int j = 0; j < 16; j++) s = fmaf(h[j], w2s[j * 7 + c], s);
        o[c] = s;
    }
    o[7] = 0.f;

    float4* op = reinterpret_cast<float4*>(g_h2 + (size_t)n * 8);
    op[0] = make_float4(o[0], o[1], o[2], o[3]);
    op[1] = make_float4(o[4], o[5], o[6], o[7]);
}

// ---------------------------------------------------------------------------
// Scatter2: agg2[dst] += h2[src].  2 lanes per edge, 16 edges per warp.
// ---------------------------------------------------------------------------
__global__ __launch_bounds__(256) void k_scatter2(const void* __restrict__ ei) {
    int warpGlobal = (blockIdx.x * 256 + threadIdx.x) >> 5;
    int lane = threadIdx.x & 31;
    int e_base = warpGlobal * 16;                 // EE = 25000*8*16 exactly
    int s = 0, d = 0;
    if (lane < 16) {
        int e = e_base + lane;
        if (g_is64) {
            const long long* p = (const long long*)ei;
            s = (int)p[e];
            d = (int)p[EE + e];
        } else {
            const int* p = (const int*)ei;
            s = p[e];
            d = p[EE + e];
        }
    }
    int eloc = lane >> 1;
    int src = __shfl_sync(0xffffffffu, s, eloc);
    int dst = __shfl_sync(0xffffffffu, d, eloc);
    if ((unsigned)src >= NN || (unsigned)dst >= NN) return;
    int chunk = lane & 1;
    float4 v = reinterpret_cast<const float4*>(g_h2)[src * 2 + chunk];
    red_add_v4(g_agg2 + (size_t)dst * 8 + chunk * 4, v);
}

// ---------------------------------------------------------------------------
// Epilogue: out[n][c] = agg2[n][c] + b2[c]
// ---------------------------------------------------------------------------
__global__ void k_final(const float* __restrict__ b2, float* __restrict__ out) {
    int i = blockIdx.x * blockDim.x + threadIdx.x;
    if (i >= NN * N_CLS) return;
    int n = i / 7;
    int c = i - n * 7;
    out[i] = g_agg2[n * 8 + c] + b2[c];
}

// ---------------------------------------------------------------------------
extern "C" void kernel_launch(void* const* d_in, const int* in_sizes, int n_in,
                              void* d_out, int out_size) {
    // Map inputs by element count (all six are distinct) — immune to ordering.
    const float* x  = nullptr;
    const void*  ei = nullptr;
    const float* W1 = nullptr;
    const float* b1 = nullptr;
    const float* W2 = nullptr;
    const float* b2 = nullptr;
    for (int i = 0; i < n_in; i++) {
        switch (in_sizes[i]) {
            case NN * D_IN:        x  = (const float*)d_in[i]; break;  // 51,200,000
            case 2 * EE:           ei = d_in[i];                break;  // 6,400,000
            case D_IN * D_HID:     W1 = (const float*)d_in[i]; break;  // 8192
            case D_HID:            b1 = (const float*)d_in[i]; break;  // 16
            case D_HID * N_CLS:    W2 = (const float*)d_in[i]; break;  // 112
            case N_CLS:            b2 = (const float*)d_in[i]; break;  // 7
            default: break;
        }
    }
    float* out = (float*)d_out;

    k_gemm1<<<G1_BLOCKS, G1_T>>>(x, W1, (const int*)ei);
    k_scatter1<<<EE / 64, 256>>>(ei);
    k_gemm2<<<(NN + 255) / 256, 256>>>(b1, W2);
    k_scatter2<<<EE / 128, 256>>>(ei);
    k_final<<<(NN * N_CLS + 255) / 256, 256>>>(b2, out);
}